// round 17
// baseline (speedup 1.0000x reference)
#include <cuda_runtime.h>
#include <cuda_fp16.h>
#include <math.h>
#include <stdint.h>

// Problem constants (fixed by the dataset)
#define BB   32
#define TT   2048
#define DD   1024
#define AA   1024
#define MTOT (BB * TT)

// GEMM tiling: CTA 128(M) x 256(N) x 64(K), 512 threads = 16 warps (4m x 4n),
// warp tile 32x64 via mma.sync.m16n8k16 fp16. Single-pass fp16 (calibrated
// rel_err ~1.9e-4 < 1e-3). 3-stage all-cp.async pipeline.
#define BM 128
#define BN 256
#define BK 64
#define NCHUNK (DD / BK)      // 16
#define NBLK   (AA / BN)      // 4
#define NSTAGE 3

// SMEM stage: rows at 144B pitch (128B data + 16B pad) -> conflict-free
// ldmatrix (+36 banks per row mod 32 = +4 -> 8 rows hit distinct bank quads).
#define PITCH   144
#define OFF_A   0
#define OFF_B   (128 * PITCH)                 // 18432
#define STAGE_BYTES (OFF_B + 256 * PITCH)     // 55296

#define SM_WSV   0
#define SM_VV    1024
#define SM_SP    2048
#define SM_STAGE 4096
#define SMEM_TOTAL (SM_STAGE + NSTAGE * STAGE_BYTES)  // 169984 (1 CTA/SM)

// ---------------------------------------------------------------------------
// Scratch (static __device__ arrays: allocation-free, graph-capture safe)
// ---------------------------------------------------------------------------
__device__ __align__(16) __half g_hh[(size_t)MTOT * DD];  // h as fp16 [M][D]
__device__ __align__(16) __half g_ut[(size_t)AA * DD];    // U^T [A][D] fp16
__device__ float g_ws[BB * AA];          // W_a_s : [B, A]
__device__ float g_part[NBLK * MTOT];    // per-n-block score partials
__device__ float g_esc[MTOT];            // exp(scores)
__device__ float g_invden[BB];           // 1 / sum_t exp
__device__ float g_cpart[8 * BB * DD];   // ctx partials over T-chunks

// ---------------------------------------------------------------------------
// PTX helpers (base-target legal: sm_75/80+ only)
// ---------------------------------------------------------------------------
__device__ __forceinline__ uint32_t smem_u32(const void* p) {
    uint32_t a;
    asm("{ .reg .u64 t; cvta.to.shared.u64 t, %1; cvt.u32.u64 %0, t; }" : "=r"(a) : "l"(p));
    return a;
}

__device__ __forceinline__ void ldsm4(uint32_t* r, uint32_t addr) {
    asm volatile("ldmatrix.sync.aligned.m8n8.x4.shared.b16 {%0,%1,%2,%3}, [%4];"
        : "=r"(r[0]), "=r"(r[1]), "=r"(r[2]), "=r"(r[3]) : "r"(addr));
}

__device__ __forceinline__ void mma_fp16(float* d, const uint32_t* a, const uint32_t* b) {
    asm volatile("mma.sync.aligned.m16n8k16.row.col.f32.f16.f16.f32 "
        "{%0,%1,%2,%3}, {%4,%5,%6,%7}, {%8,%9}, {%0,%1,%2,%3};"
        : "+f"(d[0]), "+f"(d[1]), "+f"(d[2]), "+f"(d[3])
        : "r"(a[0]), "r"(a[1]), "r"(a[2]), "r"(a[3]), "r"(b[0]), "r"(b[1]));
}

#define CP_ASYNC16(dst, src) \
    asm volatile("cp.async.cg.shared.global [%0], [%1], 16;" :: "r"(dst), "l"(src) : "memory")
#define CP_COMMIT()  asm volatile("cp.async.commit_group;" ::: "memory")
#define CP_WAIT0()   asm volatile("cp.async.wait_group 0;" ::: "memory")
#define CP_WAIT1()   asm volatile("cp.async.wait_group 1;" ::: "memory")

// ---------------------------------------------------------------------------
// Kernel: convert h (fp32) -> fp16. One float4 per thread.
// ---------------------------------------------------------------------------
__global__ void conv_h_kernel(const float4* __restrict__ h) {
    const int idx = blockIdx.x * 256 + threadIdx.x;
    float4 x = h[idx];
    __half2 p0 = __halves2half2(__float2half(x.x), __float2half(x.y));
    __half2 p1 = __halves2half2(__float2half(x.z), __float2half(x.w));
    uint2 r;
    r.x = *reinterpret_cast<unsigned*>(&p0);
    r.y = *reinterpret_cast<unsigned*>(&p1);
    reinterpret_cast<uint2*>(g_hh)[idx] = r;
}

// ---------------------------------------------------------------------------
// Kernel: transpose U [D,A] -> Ut [A,D] fp16
// ---------------------------------------------------------------------------
__global__ void conv_u_kernel(const float* __restrict__ U) {
    __shared__ float t[32][33];
    const int n0 = blockIdx.x * 32, k0 = blockIdx.y * 32;
    for (int i = threadIdx.y; i < 32; i += 8)
        t[i][threadIdx.x] = U[(size_t)(k0 + i) * AA + n0 + threadIdx.x];
    __syncthreads();
    for (int i = threadIdx.y; i < 32; i += 8)
        g_ut[(size_t)(n0 + i) * DD + k0 + threadIdx.x] = __float2half(t[threadIdx.x][i]);
}

// ---------------------------------------------------------------------------
// Kernel: g_ws[b][a] = sum_d s[b][d] * W_a[d][a]   (fp32, exact path)
// ---------------------------------------------------------------------------
__global__ void ws_kernel(const float* __restrict__ s, const float* __restrict__ W) {
    __shared__ float ss[DD];
    const int b = blockIdx.y;
    const int a = blockIdx.x * 128 + threadIdx.x;
    for (int i = threadIdx.x; i < DD; i += 128) ss[i] = s[b * DD + i];
    __syncthreads();
    float a0 = 0.f, a1 = 0.f, a2 = 0.f, a3 = 0.f;
    for (int d = 0; d < DD; d += 4) {
        a0 += ss[d + 0] * W[(size_t)(d + 0) * AA + a];
        a1 += ss[d + 1] * W[(size_t)(d + 1) * AA + a];
        a2 += ss[d + 2] * W[(size_t)(d + 2) * AA + a];
        a3 += ss[d + 3] * W[(size_t)(d + 3) * AA + a];
    }
    g_ws[b * AA + a] = (a0 + a1) + (a2 + a3);
}

// ---------------------------------------------------------------------------
// Chunk loader: A (128 rows x 128B) + B (256 rows x 128B), all cp.async.
// A: 1024 x 16B -> 2/thread.  B: 2048 x 16B -> 4/thread.
// ---------------------------------------------------------------------------
__device__ __forceinline__ void issue_chunk(uint32_t st_u32, int tid,
        const __half* __restrict__ Ah,
        const __half* __restrict__ Bh, int kt) {
#pragma unroll
    for (int i = 0; i < 2; i++) {
        const int c = tid + i * 512;
        const int row = c >> 3, o = c & 7;
        CP_ASYNC16(st_u32 + OFF_A + (uint32_t)(row * PITCH + o * 16),
                   Ah + (size_t)row * DD + kt + o * 8);
    }
#pragma unroll
    for (int i = 0; i < 4; i++) {
        const int c = tid + i * 512;
        const int row = c >> 3, o = c & 7;
        CP_ASYNC16(st_u32 + OFF_B + (uint32_t)(row * PITCH + o * 16),
                   Bh + (size_t)row * DD + kt + o * 8);
    }
    CP_COMMIT();
}

// ---------------------------------------------------------------------------
// Main kernel: fp16 HMMA GEMM (scores = h.U, fp32 accum) fused with
// tanh(.+ws).v epilogue -> per-n-block score partials.
// grid (NBLK, 512), block 512, dyn smem 169984
// ---------------------------------------------------------------------------
__global__ void __launch_bounds__(512, 1)
score_gemm(const float* __restrict__ v) {
    extern __shared__ char smem[];
    float* sws = reinterpret_cast<float*>(smem + SM_WSV);
    float* sv  = reinterpret_cast<float*>(smem + SM_VV);
    float* sp  = reinterpret_cast<float*>(smem + SM_SP);

    const int tid  = threadIdx.x;
    const int lane = tid & 31, wid = tid >> 5;
    const int wm = wid & 3;        // 4 m-slabs of 32
    const int wn = wid >> 2;       // 4 n-slabs of 64
    const int nb = blockIdx.x, n0 = nb * BN;
    const int m0 = blockIdx.y * BM;
    const int b  = m0 >> 11;       // T=2048, 128 | T

    if (tid < 256) {
        sws[tid] = g_ws[b * AA + n0 + tid];
        sv[tid]  = v[n0 + tid];
    }

    const __half* Ah = g_hh + (size_t)m0 * DD;
    const __half* Bh = g_ut + (size_t)n0 * DD;
    const uint32_t st0 = smem_u32(smem + SM_STAGE);

    float acc[2][8][4];
#pragma unroll
    for (int i = 0; i < 2; i++)
#pragma unroll
        for (int j = 0; j < 8; j++)
#pragma unroll
            for (int k = 0; k < 4; k++) acc[i][j][k] = 0.f;

    // ldmatrix per-lane address components
    const int a_row  = wm * 32 + (lane & 15);                     // + mf*16
    const int a_koff = (lane >> 4) * 16;                          // + ks*32
    const int b_row  = wn * 64 + (lane & 7) + ((lane >> 4) << 3); // + pair*16
    const int b_koff = ((lane >> 3) & 1) * 16;                    // + ks*32

    // prologue: chunks 0, 1 in flight
    issue_chunk(st0 + 0 * STAGE_BYTES, tid, Ah, Bh, 0);
    issue_chunk(st0 + 1 * STAGE_BYTES, tid, Ah, Bh, BK);

    int stage = 0;
    for (int c = 0; c < NCHUNK; c++) {
        if (c + 2 < NCHUNK) { CP_WAIT1(); } else { CP_WAIT0(); }
        __syncthreads();   // chunk c resident everywhere; stage (c+2)%3 free

        if (c + 2 < NCHUNK) {
            int ns = stage + 2; if (ns >= NSTAGE) ns -= NSTAGE;
            issue_chunk(st0 + ns * STAGE_BYTES, tid, Ah, Bh, (c + 2) * BK);
        }

        const uint32_t cb = st0 + stage * STAGE_BYTES;
        const uint32_t aH = cb + OFF_A + a_row * PITCH + a_koff;
        const uint32_t bH = cb + OFF_B + b_row * PITCH + b_koff;

#pragma unroll
        for (int ks = 0; ks < 4; ks++) {   // 4 K=16 steps per 64-chunk
            uint32_t ah[2][4], bb[8][2];
            ldsm4(ah[0], aH + ks * 32);
            ldsm4(ah[1], aH + 16 * PITCH + ks * 32);
#pragma unroll
            for (int p = 0; p < 4; p++) {
                uint32_t r[4];
                ldsm4(r, bH + p * (16 * PITCH) + ks * 32);
                bb[2*p][0] = r[0];   bb[2*p][1] = r[1];
                bb[2*p+1][0] = r[2]; bb[2*p+1][1] = r[3];
            }
#pragma unroll
            for (int mf = 0; mf < 2; mf++)
#pragma unroll
                for (int nf = 0; nf < 8; nf++) mma_fp16(acc[mf][nf], ah[mf], bb[nf]);
        }

        if (++stage >= NSTAGE) stage = 0;
        __syncthreads();   // all warps done reading stage c before it is refilled
    }

    // ---- epilogue: tanh(acc + ws) . v  ->  per-row partials -----------------
    // C frag (mf,nf): rows wm*32+mf*16+{lane/4, lane/4+8}, cols wn*64+nf*8+2(lane%4)+{0,1}
    float rp[2][2] = {{0.f, 0.f}, {0.f, 0.f}};
#pragma unroll
    for (int mf = 0; mf < 2; mf++)
#pragma unroll
        for (int nf = 0; nf < 8; nf++) {
            const int col = wn * 64 + nf * 8 + 2 * (lane & 3);
            const float w0 = sws[col], w1 = sws[col + 1];
            const float v0 = sv[col],  v1 = sv[col + 1];
            rp[mf][0] += v0 * tanhf(acc[mf][nf][0] + w0) + v1 * tanhf(acc[mf][nf][1] + w1);
            rp[mf][1] += v0 * tanhf(acc[mf][nf][2] + w0) + v1 * tanhf(acc[mf][nf][3] + w1);
        }
#pragma unroll
    for (int mf = 0; mf < 2; mf++)
#pragma unroll
        for (int rb = 0; rb < 2; rb++) {
            float ssum = rp[mf][rb];
            ssum += __shfl_xor_sync(0xffffffffu, ssum, 1);
            ssum += __shfl_xor_sync(0xffffffffu, ssum, 2);
            if ((lane & 3) == 0) {
                const int row = wm * 32 + mf * 16 + rb * 8 + (lane >> 2);
                sp[row * 4 + wn] = ssum;
            }
        }
    __syncthreads();
    if (tid < 128)
        g_part[(size_t)nb * MTOT + m0 + tid] =
            (sp[tid * 4] + sp[tid * 4 + 1]) + (sp[tid * 4 + 2] + sp[tid * 4 + 3]);
}

// ---------------------------------------------------------------------------
// Kernel: scores = sum of NBLK partials; e = exp(score) (raw, per reference);
// g_invden[b] = 1 / sum_t e.
// ---------------------------------------------------------------------------
__global__ void softmax_kernel() {
    const int b = blockIdx.x;
    __shared__ float red[512];
    float local = 0.f;
    for (int t = threadIdx.x; t < TT; t += 512) {
        const int m = b * TT + t;
        float sc = 0.f;
#pragma unroll
        for (int p = 0; p < NBLK; p++) sc += g_part[(size_t)p * MTOT + m];
        const float e = expf(sc);
        g_esc[m] = e;
        local += e;
    }
    red[threadIdx.x] = local;
    __syncthreads();
    for (int s = 256; s > 0; s >>= 1) {
        if (threadIdx.x < s) red[threadIdx.x] += red[threadIdx.x + s];
        __syncthreads();
    }
    if (threadIdx.x == 0) g_invden[b] = 1.0f / red[0];
}

// ---------------------------------------------------------------------------
// Context: c[b][d] = (sum_t e*h) * invden — T split into 8 chunks (1024 CTAs)
// then reduced. Memory-bound single pass over h (fp32, exact).
// ---------------------------------------------------------------------------
__global__ void ctx_part_kernel(const float* __restrict__ h) {
    const int b = blockIdx.y;
    const int d = blockIdx.x * 256 + threadIdx.x;
    const int tc = blockIdx.z;
    __shared__ float w[256];
    const float* hb = h + (size_t)b * TT * DD + (size_t)tc * 256 * DD;
    w[threadIdx.x] = g_esc[b * TT + tc * 256 + threadIdx.x];
    __syncthreads();
    float a0 = 0.f, a1 = 0.f;
#pragma unroll 8
    for (int i = 0; i < 256; i += 2) {
        a0 += w[i + 0] * hb[(size_t)(i + 0) * DD + d];
        a1 += w[i + 1] * hb[(size_t)(i + 1) * DD + d];
    }
    g_cpart[((size_t)tc * BB + b) * DD + d] = a0 + a1;
}

__global__ void ctx_reduce_kernel(float* __restrict__ out) {
    const int b = blockIdx.y;
    const int d = blockIdx.x * 256 + threadIdx.x;
    float s = 0.f;
#pragma unroll
    for (int p = 0; p < 8; p++) s += g_cpart[((size_t)p * BB + b) * DD + d];
    out[b * DD + d] = s * g_invden[b];
}

// ---------------------------------------------------------------------------
// Launch (graph-capturable: kernels only)
// Inputs: s, h, W_a, U_a, v_a (all float32)
// ---------------------------------------------------------------------------
extern "C" void kernel_launch(void* const* d_in, const int* in_sizes, int n_in,
                              void* d_out, int out_size) {
    const float* s  = (const float*)d_in[0];
    const float* h  = (const float*)d_in[1];
    const float* Wa = (const float*)d_in[2];
    const float* Ua = (const float*)d_in[3];
    const float* va = (const float*)d_in[4];
    float* out = (float*)d_out;

    cudaFuncSetAttribute(score_gemm,
                         cudaFuncAttributeMaxDynamicSharedMemorySize, SMEM_TOTAL);

    conv_h_kernel    <<<65536, 256>>>((const float4*)h);
    conv_u_kernel    <<<dim3(32, 32), dim3(32, 8)>>>(Ua);
    ws_kernel        <<<dim3(8, 32), 128>>>(s, Wa);
    score_gemm       <<<dim3(NBLK, MTOT / BM), 512, SMEM_TOTAL>>>(va);
    softmax_kernel   <<<32, 512>>>();
    ctx_part_kernel  <<<dim3(4, 32, 8), 256>>>(h);
    ctx_reduce_kernel<<<dim3(4, 32), 256>>>(out);
}